// round 8
// baseline (speedup 1.0000x reference)
#include <cuda_runtime.h>
#include <cuda_bf16.h>

// Mat2Twist: out[b] = theta * axis, theta = acos((tr-1)/2),
// axis = (m21-m12, m02-m20, m10-m01) / (2*sin(theta)).
// Uses sin(acos(c)) == sqrt(1-c^2) (exact for theta in (0, pi)).
//
// Vectorized: each thread handles 4 matrices = 36 floats = 9 float4 loads,
// 12 output floats = 3 float4 stores. All accesses 16B-aligned & coalesced.

__device__ __forceinline__ float twist_factor(float tr) {
    float c = 0.5f * (tr - 1.0f);
    c = fminf(fmaxf(c, -1.0f), 1.0f);
    float ang = acosf(c);
    float s2  = fmaxf(fmaf(-c, c, 1.0f), 1e-20f);  // 1 - c^2 = (2 sin theta / 2)^2
    return 0.5f * ang * rsqrtf(s2);                // theta / (2 sin theta)
}

__global__ __launch_bounds__(256)
void mat2twist_vec4_kernel(const float4* __restrict__ in,
                           float4* __restrict__ out, int nq) {
    int t = blockIdx.x * blockDim.x + threadIdx.x;
    if (t >= nq) return;

    const float4* ip = in + (size_t)t * 9;
    float4 v[9];
#pragma unroll
    for (int i = 0; i < 9; ++i) v[i] = ip[i];

    float m[36];
#pragma unroll
    for (int i = 0; i < 9; ++i) {
        m[4 * i + 0] = v[i].x;
        m[4 * i + 1] = v[i].y;
        m[4 * i + 2] = v[i].z;
        m[4 * i + 3] = v[i].w;
    }

    float4 o[3];
    float* op = reinterpret_cast<float*>(o);
#pragma unroll
    for (int j = 0; j < 4; ++j) {
        const float* a = m + 9 * j;
        float f = twist_factor(a[0] + a[4] + a[8]);
        op[3 * j + 0] = f * (a[7] - a[5]);  // m21 - m12
        op[3 * j + 1] = f * (a[2] - a[6]);  // m02 - m20
        op[3 * j + 2] = f * (a[3] - a[1]);  // m10 - m01
    }

    float4* outp = out + (size_t)t * 3;
    outp[0] = o[0];
    outp[1] = o[1];
    outp[2] = o[2];
}

// Scalar tail for n % 4 != 0 (not hit for B=4194304, kept for safety).
__global__ void mat2twist_tail_kernel(const float* __restrict__ in,
                                      float* __restrict__ out,
                                      int start, int n) {
    int i = start + blockIdx.x * blockDim.x + threadIdx.x;
    if (i >= n) return;
    const float* a = in + (size_t)i * 9;
    float f = twist_factor(a[0] + a[4] + a[8]);
    float* o = out + (size_t)i * 3;
    o[0] = f * (a[7] - a[5]);
    o[1] = f * (a[2] - a[6]);
    o[2] = f * (a[3] - a[1]);
}

extern "C" void kernel_launch(void* const* d_in, const int* in_sizes, int n_in,
                              void* d_out, int out_size) {
    const float* in = (const float*)d_in[0];
    float* out = (float*)d_out;
    int n  = in_sizes[0] / 9;   // number of 3x3 matrices
    int nq = n / 4;             // quads of matrices (float4-aligned path)
    int rem = n - nq * 4;

    if (nq > 0) {
        int threads = 256;
        int blocks = (nq + threads - 1) / threads;
        mat2twist_vec4_kernel<<<blocks, threads>>>(
            (const float4*)in, (float4*)out, nq);
    }
    if (rem > 0) {
        mat2twist_tail_kernel<<<1, 32>>>(in, out, nq * 4, n);
    }
}

// round 9
// speedup vs baseline: 1.0317x; 1.0317x over previous
#include <cuda_runtime.h>
#include <cuda_bf16.h>

// Mat2Twist: out[b] = theta * axis, theta = acos((tr-1)/2),
// axis = (m21-m12, m02-m20, m10-m01) / (2*sin(theta)).
// Uses sin(acos(c)) == sqrt(1-c^2), exact on theta in (0, pi).
//
// R9: shared-memory staging so ALL global traffic is coalesced float4.
//   - 256 threads/block, 1024 matrices/block.
//   - load: 9 float4/thread, lane-consecutive (4 wavefronts per LDG.128).
//   - smem compute: thread t handles matrices t+256k; LDS base stride 9*t
//     floats (gcd(9,32)=1 -> conflict-free). Result write stride 3*t floats,
//     also conflict-free. Output reuses the same smem buffer.
//   - store: 3 float4/thread, lane-consecutive.

__device__ __forceinline__ float twist_factor(float tr) {
    float c = 0.5f * (tr - 1.0f);
    c = fminf(fmaxf(c, -1.0f), 1.0f);
    float ang = acosf(c);
    float s2  = fmaxf(fmaf(-c, c, 1.0f), 1e-20f);  // 1 - c^2
    return 0.5f * ang * rsqrtf(s2);                // theta / (2 sin theta)
}

constexpr int THREADS = 256;
constexpr int MPB     = 1024;            // matrices per block
constexpr int IN_F4   = MPB * 9 / 4;     // 2304 float4 in
constexpr int OUT_F4  = MPB * 3 / 4;     // 768 float4 out

__global__ __launch_bounds__(THREADS)
void mat2twist_smem_kernel(const float4* __restrict__ in,
                           float4* __restrict__ out) {
    __shared__ float s[MPB * 9];  // 36 KB, reused for output
    float4* s4 = reinterpret_cast<float4*>(s);
    const int tid = threadIdx.x;

    // ---- coalesced load: 9 float4 per thread ----
    const float4* ip = in + (size_t)blockIdx.x * IN_F4;
#pragma unroll
    for (int k = 0; k < 9; ++k)
        s4[k * THREADS + tid] = ip[k * THREADS + tid];
    __syncthreads();

    // ---- compute 4 matrices per thread (strided, conflict-free LDS) ----
    float r[12];
#pragma unroll
    for (int k = 0; k < 4; ++k) {
        const float* a = s + 9 * (tid + k * THREADS);
        float m1 = a[1], m2 = a[2], m3 = a[3];
        float m5 = a[5], m6 = a[6], m7 = a[7];
        float f  = twist_factor(a[0] + a[4] + a[8]);
        r[3 * k + 0] = f * (m7 - m5);  // m21 - m12
        r[3 * k + 1] = f * (m2 - m6);  // m02 - m20
        r[3 * k + 2] = f * (m3 - m1);  // m10 - m01
    }
    __syncthreads();

    // ---- stage results into smem (conflict-free: stride 3*tid) ----
#pragma unroll
    for (int k = 0; k < 4; ++k) {
        float* o = s + 3 * (tid + k * THREADS);
        o[0] = r[3 * k + 0];
        o[1] = r[3 * k + 1];
        o[2] = r[3 * k + 2];
    }
    __syncthreads();

    // ---- coalesced store: 3 float4 per thread ----
    float4* op = out + (size_t)blockIdx.x * OUT_F4;
#pragma unroll
    for (int k = 0; k < 3; ++k)
        op[k * THREADS + tid] = s4[k * THREADS + tid];
}

// Scalar tail for n % MPB != 0 (not hit for B=4194304, kept for safety).
__global__ void mat2twist_tail_kernel(const float* __restrict__ in,
                                      float* __restrict__ out,
                                      int start, int n) {
    int i = start + blockIdx.x * blockDim.x + threadIdx.x;
    if (i >= n) return;
    const float* a = in + (size_t)i * 9;
    float f = twist_factor(a[0] + a[4] + a[8]);
    float* o = out + (size_t)i * 3;
    o[0] = f * (a[7] - a[5]);
    o[1] = f * (a[2] - a[6]);
    o[2] = f * (a[3] - a[1]);
}

extern "C" void kernel_launch(void* const* d_in, const int* in_sizes, int n_in,
                              void* d_out, int out_size) {
    const float* in = (const float*)d_in[0];
    float* out = (float*)d_out;
    int n = in_sizes[0] / 9;        // number of 3x3 matrices
    int nblocks = n / MPB;          // full blocks (B=4194304 -> 4096)
    int done = nblocks * MPB;
    int rem = n - done;

    if (nblocks > 0) {
        mat2twist_smem_kernel<<<nblocks, THREADS>>>(
            (const float4*)in, (float4*)out);
    }
    if (rem > 0) {
        int tthreads = 256;
        int tblocks = (rem + tthreads - 1) / tthreads;
        mat2twist_tail_kernel<<<tblocks, tthreads>>>(in, out, done, n);
    }
}

// round 10
// speedup vs baseline: 1.2025x; 1.1656x over previous
#include <cuda_runtime.h>
#include <cuda_bf16.h>

// Mat2Twist: out[b] = theta * axis, theta = acos((tr-1)/2),
// axis = (m21-m12, m02-m20, m10-m01) / (2*sin(theta)).
// Uses sin(acos(c)) == sqrt(1-c^2), exact on theta in (0, pi).
//
// R10: cp.async double-buffered pipeline. Load issue is decoupled from
// compute so DRAM demand is continuous (R9 was phase-gated at 62% DRAM).
//   tile = 512 matrices = 18KB; 2 in-buffers + 6KB out staging = 42KB smem
//   -> 5 blocks/SM. Grid-stride over tiles, one commit_group per iteration.

__device__ __forceinline__ float twist_factor(float tr) {
    float c = 0.5f * (tr - 1.0f);
    c = fminf(fmaxf(c, -1.0f), 1.0f);
    float ang = acosf(c);
    float s2  = fmaxf(fmaf(-c, c, 1.0f), 1e-20f);  // 1 - c^2
    return 0.5f * ang * rsqrtf(s2);                // theta / (2 sin theta)
}

constexpr int THREADS = 256;
constexpr int TILE    = 512;            // matrices per tile
constexpr int T_INF4  = TILE * 9 / 4;   // 1152 float4 in per tile
constexpr int T_OUTF4 = TILE * 3 / 4;   // 384 float4 out per tile

__device__ __forceinline__ void cp_async16(void* smem_ptr, const void* gptr) {
    unsigned s = (unsigned)__cvta_generic_to_shared(smem_ptr);
    asm volatile("cp.async.cg.shared.global [%0], [%1], 16;\n"
                 :: "r"(s), "l"(gptr));
}
__device__ __forceinline__ void cp_commit() {
    asm volatile("cp.async.commit_group;\n" ::: "memory");
}
template <int N>
__device__ __forceinline__ void cp_wait() {
    asm volatile("cp.async.wait_group %0;\n" :: "n"(N) : "memory");
}

__global__ __launch_bounds__(THREADS)
void mat2twist_pipe_kernel(const float4* __restrict__ in,
                           float4* __restrict__ out, int ntiles) {
    __shared__ float sbuf[2][TILE * 9];  // 2 x 18KB input buffers
    __shared__ float sout[TILE * 3];     // 6KB output staging
    const int tid = threadIdx.x;

    const int t0     = blockIdx.x;
    const int stride = gridDim.x;

    // prologue: prefetch first two tiles
    for (int p = 0; p < 2; ++p) {
        int tile = t0 + p * stride;
        if (tile < ntiles) {
            const float4* gp = in + (size_t)tile * T_INF4;
            float4* sp = reinterpret_cast<float4*>(sbuf[p]);
#pragma unroll
            for (int i = tid; i < T_INF4; i += THREADS)
                cp_async16(&sp[i], &gp[i]);
        }
        cp_commit();
    }

    int buf = 0;
    for (int t = t0; t < ntiles; t += stride, buf ^= 1) {
        cp_wait<1>();          // current buffer's tile is resident
        __syncthreads();

        // compute: thread handles matrices tid and tid+256 of this tile
        const float* sb = sbuf[buf];
#pragma unroll
        for (int k = 0; k < TILE / THREADS; ++k) {
            int ml = tid + k * THREADS;
            const float* a = sb + 9 * ml;     // stride-9 base: conflict-free
            float m1 = a[1], m2 = a[2], m3 = a[3];
            float m5 = a[5], m6 = a[6], m7 = a[7];
            float f  = twist_factor(a[0] + a[4] + a[8]);
            float* o = sout + 3 * ml;         // stride-3 base: conflict-free
            o[0] = f * (m7 - m5);             // m21 - m12
            o[1] = f * (m2 - m6);             // m02 - m20
            o[2] = f * (m3 - m1);             // m10 - m01
        }
        __syncthreads();       // sout ready; sbuf[buf] fully consumed

        // coalesced float4 store of this tile's output
        float4* op = out + (size_t)t * T_OUTF4;
        const float4* so4 = reinterpret_cast<const float4*>(sout);
#pragma unroll
        for (int i = tid; i < T_OUTF4; i += THREADS)
            op[i] = so4[i];

        // prefetch tile t + 2*stride into the buffer just freed
        int nt = t + 2 * stride;
        if (nt < ntiles) {
            const float4* gp = in + (size_t)nt * T_INF4;
            float4* sp = reinterpret_cast<float4*>(sbuf[buf]);
#pragma unroll
            for (int i = tid; i < T_INF4; i += THREADS)
                cp_async16(&sp[i], &gp[i]);
        }
        cp_commit();           // exactly one group per iteration (may be empty)
    }
    cp_wait<0>();              // drain before exit
}

// Scalar tail for n % TILE != 0 (not hit for B=4194304, kept for safety).
__global__ void mat2twist_tail_kernel(const float* __restrict__ in,
                                      float* __restrict__ out,
                                      int start, int n) {
    int i = start + blockIdx.x * blockDim.x + threadIdx.x;
    if (i >= n) return;
    const float* a = in + (size_t)i * 9;
    float f = twist_factor(a[0] + a[4] + a[8]);
    float* o = out + (size_t)i * 3;
    o[0] = f * (a[7] - a[5]);
    o[1] = f * (a[2] - a[6]);
    o[2] = f * (a[3] - a[1]);
}

extern "C" void kernel_launch(void* const* d_in, const int* in_sizes, int n_in,
                              void* d_out, int out_size) {
    const float* in = (const float*)d_in[0];
    float* out = (float*)d_out;
    int n = in_sizes[0] / 9;        // number of 3x3 matrices
    int ntiles = n / TILE;          // full tiles (B=4194304 -> 8192)
    int done = ntiles * TILE;
    int rem = n - done;

    if (ntiles > 0) {
        // 152 SMs x 5 blocks/SM (42KB smem/block); grid-stride covers the rest
        int grid = 152 * 5;
        if (grid > ntiles) grid = ntiles;
        mat2twist_pipe_kernel<<<grid, THREADS>>>(
            (const float4*)in, (float4*)out, ntiles);
    }
    if (rem > 0) {
        int tthreads = 256;
        int tblocks = (rem + tthreads - 1) / tthreads;
        mat2twist_tail_kernel<<<tblocks, tthreads>>>(in, out, done, n);
    }
}

// round 12
// speedup vs baseline: 1.2101x; 1.0063x over previous
#include <cuda_runtime.h>
#include <cuda_bf16.h>

// Mat2Twist: out[b] = theta * axis, theta = acos((tr-1)/2),
// axis = (m21-m12, m02-m20, m10-m01) / (2*sin(theta)).
// Uses sin(acos(c)) == sqrt(1-c^2), exact on theta in (0, pi).
//
// R12: R11 (3-stage cp.async ring, TILE=256, 30KB smem, 7 blocks/SM) with
// the missing ring-index advance fixed (R11 computed sbuf[0] every
// iteration -> raced its own prefetch).

__device__ __forceinline__ float twist_factor(float tr) {
    float c = 0.5f * (tr - 1.0f);
    c = fminf(fmaxf(c, -1.0f), 1.0f);
    float ang = acosf(c);
    float s2  = fmaxf(fmaf(-c, c, 1.0f), 1e-20f);  // 1 - c^2
    return 0.5f * ang * rsqrtf(s2);                // theta / (2 sin theta)
}

constexpr int THREADS = 256;
constexpr int TILE    = 256;            // matrices per tile
constexpr int T_INF4  = TILE * 9 / 4;   // 576 float4 in per tile
constexpr int T_OUTF4 = TILE * 3 / 4;   // 192 float4 out per tile
constexpr int STAGES  = 3;

__device__ __forceinline__ void cp_async16(void* smem_ptr, const void* gptr) {
    unsigned s = (unsigned)__cvta_generic_to_shared(smem_ptr);
    asm volatile("cp.async.cg.shared.global [%0], [%1], 16;\n"
                 :: "r"(s), "l"(gptr));
}
__device__ __forceinline__ void cp_commit() {
    asm volatile("cp.async.commit_group;\n" ::: "memory");
}
template <int N>
__device__ __forceinline__ void cp_wait() {
    asm volatile("cp.async.wait_group %0;\n" :: "n"(N) : "memory");
}

__global__ __launch_bounds__(THREADS)
void mat2twist_pipe3_kernel(const float4* __restrict__ in,
                            float4* __restrict__ out, int ntiles) {
    __shared__ float sbuf[STAGES][TILE * 9];  // 3 x 9KB input ring
    __shared__ float sout[TILE * 3];          // 3KB output staging
    const int tid = threadIdx.x;

    const int t0     = blockIdx.x;
    const int stride = gridDim.x;

    // prologue: prefetch first STAGES tiles (empty groups keep FIFO exact)
#pragma unroll
    for (int p = 0; p < STAGES; ++p) {
        long long tile = (long long)t0 + (long long)p * stride;
        if (tile < ntiles) {
            const float4* gp = in + (size_t)tile * T_INF4;
            float4* sp = reinterpret_cast<float4*>(sbuf[p]);
#pragma unroll
            for (int i = tid; i < T_INF4; i += THREADS)
                cp_async16(&sp[i], &gp[i]);
        }
        cp_commit();
    }

    int buf = 0;
    for (int t = t0; t < ntiles; t += stride) {
        cp_wait<STAGES - 1>();   // oldest in-flight group (= this buf) done
        __syncthreads();

        // compute: one matrix per thread (stride-9 LDS base: conflict-free)
        const float* sb = sbuf[buf];
        {
            const float* a = sb + 9 * tid;
            float m1 = a[1], m2 = a[2], m3 = a[3];
            float m5 = a[5], m6 = a[6], m7 = a[7];
            float f  = twist_factor(a[0] + a[4] + a[8]);
            float* o = sout + 3 * tid;        // stride-3: conflict-free
            o[0] = f * (m7 - m5);             // m21 - m12
            o[1] = f * (m2 - m6);             // m02 - m20
            o[2] = f * (m3 - m1);             // m10 - m01
        }
        __syncthreads();         // sout ready; sbuf[buf] fully consumed

        // prefetch tile t + STAGES*stride into the buffer just freed
        // (issued BEFORE the store so loads hit DRAM earlier)
        long long nt = (long long)t + (long long)STAGES * stride;
        if (nt < ntiles) {
            const float4* gp = in + (size_t)nt * T_INF4;
            float4* sp = reinterpret_cast<float4*>(sbuf[buf]);
#pragma unroll
            for (int i = tid; i < T_INF4; i += THREADS)
                cp_async16(&sp[i], &gp[i]);
        }
        cp_commit();             // exactly one group per iteration

        // coalesced float4 store of this tile's output
        float4* op = out + (size_t)t * T_OUTF4;
        const float4* so4 = reinterpret_cast<const float4*>(sout);
#pragma unroll
        for (int i = tid; i < T_OUTF4; i += THREADS)
            op[i] = so4[i];

        buf = (buf == STAGES - 1) ? 0 : buf + 1;   // <-- R11's missing line
    }
    cp_wait<0>();                // drain before exit
}

// Scalar tail for n % TILE != 0 (not hit for B=4194304, kept for safety).
__global__ void mat2twist_tail_kernel(const float* __restrict__ in,
                                      float* __restrict__ out,
                                      int start, int n) {
    int i = start + blockIdx.x * blockDim.x + threadIdx.x;
    if (i >= n) return;
    const float* a = in + (size_t)i * 9;
    float f = twist_factor(a[0] + a[4] + a[8]);
    float* o = out + (size_t)i * 3;
    o[0] = f * (a[7] - a[5]);
    o[1] = f * (a[2] - a[6]);
    o[2] = f * (a[3] - a[1]);
}

extern "C" void kernel_launch(void* const* d_in, const int* in_sizes, int n_in,
                              void* d_out, int out_size) {
    const float* in = (const float*)d_in[0];
    float* out = (float*)d_out;
    int n = in_sizes[0] / 9;        // number of 3x3 matrices
    int ntiles = n / TILE;          // full tiles (B=4194304 -> 16384)
    int done = ntiles * TILE;
    int rem = n - done;

    if (ntiles > 0) {
        // 152 SMs x 7 blocks/SM (30KB smem/block)
        int grid = 152 * 7;
        if (grid > ntiles) grid = ntiles;
        mat2twist_pipe3_kernel<<<grid, THREADS>>>(
            (const float4*)in, (float4*)out, ntiles);
    }
    if (rem > 0) {
        int tthreads = 256;
        int tblocks = (rem + tthreads - 1) / tthreads;
        mat2twist_tail_kernel<<<tblocks, tthreads>>>(in, out, done, n);
    }
}

// round 13
// speedup vs baseline: 1.2112x; 1.0009x over previous
#include <cuda_runtime.h>
#include <cuda_bf16.h>

// Mat2Twist: out[b] = theta * axis, theta = acos((tr-1)/2),
// axis = (m21-m12, m02-m20, m10-m01) / (2*sin(theta)).
// Uses sin(acos(c)) == sqrt(1-c^2), exact on theta in (0, pi).
//
// R13: R12 (3-stage cp.async ring, TILE=256, 30KB smem) with:
//   - grid = 1024: exactly ntiles/grid = 16 tiles per block (B=4194304),
//     all blocks resident (capacity 7/SM x 152 = 1064) -> no straggler wave.
//   - streaming stores (__stcs) for the write-once output stream to avoid
//     evicting read sectors from L2.

__device__ __forceinline__ float twist_factor(float tr) {
    float c = 0.5f * (tr - 1.0f);
    c = fminf(fmaxf(c, -1.0f), 1.0f);
    float ang = acosf(c);
    float s2  = fmaxf(fmaf(-c, c, 1.0f), 1e-20f);  // 1 - c^2
    return 0.5f * ang * rsqrtf(s2);                // theta / (2 sin theta)
}

constexpr int THREADS = 256;
constexpr int TILE    = 256;            // matrices per tile
constexpr int T_INF4  = TILE * 9 / 4;   // 576 float4 in per tile
constexpr int T_OUTF4 = TILE * 3 / 4;   // 192 float4 out per tile
constexpr int STAGES  = 3;

__device__ __forceinline__ void cp_async16(void* smem_ptr, const void* gptr) {
    unsigned s = (unsigned)__cvta_generic_to_shared(smem_ptr);
    asm volatile("cp.async.cg.shared.global [%0], [%1], 16;\n"
                 :: "r"(s), "l"(gptr));
}
__device__ __forceinline__ void cp_commit() {
    asm volatile("cp.async.commit_group;\n" ::: "memory");
}
template <int N>
__device__ __forceinline__ void cp_wait() {
    asm volatile("cp.async.wait_group %0;\n" :: "n"(N) : "memory");
}

__global__ __launch_bounds__(THREADS)
void mat2twist_pipe3_kernel(const float4* __restrict__ in,
                            float4* __restrict__ out, int ntiles) {
    __shared__ float sbuf[STAGES][TILE * 9];  // 3 x 9KB input ring
    __shared__ float sout[TILE * 3];          // 3KB output staging
    const int tid = threadIdx.x;

    const int t0     = blockIdx.x;
    const int stride = gridDim.x;

    // prologue: prefetch first STAGES tiles (empty groups keep FIFO exact)
#pragma unroll
    for (int p = 0; p < STAGES; ++p) {
        long long tile = (long long)t0 + (long long)p * stride;
        if (tile < ntiles) {
            const float4* gp = in + (size_t)tile * T_INF4;
            float4* sp = reinterpret_cast<float4*>(sbuf[p]);
#pragma unroll
            for (int i = tid; i < T_INF4; i += THREADS)
                cp_async16(&sp[i], &gp[i]);
        }
        cp_commit();
    }

    int buf = 0;
    for (int t = t0; t < ntiles; t += stride) {
        cp_wait<STAGES - 1>();   // oldest in-flight group (= this buf) done
        __syncthreads();

        // compute: one matrix per thread (stride-9 LDS base: conflict-free)
        const float* sb = sbuf[buf];
        {
            const float* a = sb + 9 * tid;
            float m1 = a[1], m2 = a[2], m3 = a[3];
            float m5 = a[5], m6 = a[6], m7 = a[7];
            float f  = twist_factor(a[0] + a[4] + a[8]);
            float* o = sout + 3 * tid;        // stride-3: conflict-free
            o[0] = f * (m7 - m5);             // m21 - m12
            o[1] = f * (m2 - m6);             // m02 - m20
            o[2] = f * (m3 - m1);             // m10 - m01
        }
        __syncthreads();         // sout ready; sbuf[buf] fully consumed

        // prefetch tile t + STAGES*stride into the buffer just freed
        // (issued BEFORE the store so loads hit DRAM earlier)
        long long nt = (long long)t + (long long)STAGES * stride;
        if (nt < ntiles) {
            const float4* gp = in + (size_t)nt * T_INF4;
            float4* sp = reinterpret_cast<float4*>(sbuf[buf]);
#pragma unroll
            for (int i = tid; i < T_INF4; i += THREADS)
                cp_async16(&sp[i], &gp[i]);
        }
        cp_commit();             // exactly one group per iteration

        // coalesced float4 streaming store of this tile's output
        float4* op = out + (size_t)t * T_OUTF4;
        const float4* so4 = reinterpret_cast<const float4*>(sout);
#pragma unroll
        for (int i = tid; i < T_OUTF4; i += THREADS)
            __stcs(&op[i], so4[i]);

        buf = (buf == STAGES - 1) ? 0 : buf + 1;
    }
    cp_wait<0>();                // drain before exit
}

// Scalar tail for n % TILE != 0 (not hit for B=4194304, kept for safety).
__global__ void mat2twist_tail_kernel(const float* __restrict__ in,
                                      float* __restrict__ out,
                                      int start, int n) {
    int i = start + blockIdx.x * blockDim.x + threadIdx.x;
    if (i >= n) return;
    const float* a = in + (size_t)i * 9;
    float f = twist_factor(a[0] + a[4] + a[8]);
    float* o = out + (size_t)i * 3;
    o[0] = f * (a[7] - a[5]);
    o[1] = f * (a[2] - a[6]);
    o[2] = f * (a[3] - a[1]);
}

extern "C" void kernel_launch(void* const* d_in, const int* in_sizes, int n_in,
                              void* d_out, int out_size) {
    const float* in = (const float*)d_in[0];
    float* out = (float*)d_out;
    int n = in_sizes[0] / 9;        // number of 3x3 matrices
    int ntiles = n / TILE;          // full tiles (B=4194304 -> 16384)
    int done = ntiles * TILE;
    int rem = n - done;

    if (ntiles > 0) {
        // grid chosen so ntiles % grid == 0 when possible -> perfect balance.
        // 1024 blocks: all resident (7/SM x 152 = 1064), 16 tiles each.
        int grid = 1024;
        if (grid > ntiles) grid = ntiles;
        while (grid > 1 && (ntiles % grid) != 0) grid--;   // keep balance
        mat2twist_pipe3_kernel<<<grid, THREADS>>>(
            (const float4*)in, (float4*)out, ntiles);
    }
    if (rem > 0) {
        int tthreads = 256;
        int tblocks = (rem + tthreads - 1) / tthreads;
        mat2twist_tail_kernel<<<tblocks, tthreads>>>(in, out, done, n);
    }
}